// round 16
// baseline (speedup 1.0000x reference)
#include <cuda_runtime.h>
#include <cuda_fp16.h>
#include <math.h>
#include <stdint.h>

// Problem constants
#define BB   4
#define NH   16
#define HD   64
#define DM   1024
#define LQ   2048
#define LK   2048
#define MTOT (BB * LQ)

// ---------------------------------------------------------------------------
// Scratch (device globals — no allocation allowed).
// Private buffer set per projection so all three GEMMs can run concurrently.
// ---------------------------------------------------------------------------
__device__ __half g_aAhi[MTOT * DM];
__device__ __half g_aAlo[MTOT * DM];
__device__ __half g_aBhi[MTOT * DM];
__device__ __half g_aBlo[MTOT * DM];
__device__ __half g_aChi[MTOT * DM];
__device__ __half g_aClo[MTOT * DM];
__device__ __half g_wAhi[DM * DM];
__device__ __half g_wAlo[DM * DM];
__device__ __half g_wBhi[DM * DM];
__device__ __half g_wBlo[DM * DM];
__device__ __half g_wChi[DM * DM];
__device__ __half g_wClo[DM * DM];
__device__ __half g_wDhi[DM * DM];
__device__ __half g_wDlo[DM * DM];
__device__ __half g_qhi[BB * NH * LQ * HD];
__device__ __half g_khi[BB * NH * LK * HD];
__device__ __half g_vh [BB * NH * LK * HD];
__device__ __half g_chi[MTOT * DM];
__device__ __half g_clo[MTOT * DM];

// ---------------------------------------------------------------------------
// Helpers (identical to R11/R14)
// ---------------------------------------------------------------------------
__device__ __forceinline__ unsigned pack_h2(__half a, __half b) {
    return (unsigned)__half_as_ushort(a) | ((unsigned)__half_as_ushort(b) << 16);
}

__device__ __forceinline__ void split2(float x, float y,
                                       unsigned& hi, unsigned& lo) {
    __half hx = __float2half_rn(x);
    __half hy = __float2half_rn(y);
    __half lx = __float2half_rn(x - __half2float(hx));
    __half ly = __float2half_rn(y - __half2float(hy));
    hi = pack_h2(hx, hy);
    lo = pack_h2(lx, ly);
}

__device__ __forceinline__ float ex2f(float x) {
    float y;
    asm("ex2.approx.ftz.f32 %0, %1;" : "=f"(y) : "f"(x));
    return y;
}

__device__ __forceinline__ unsigned f22h2(float lo, float hi) {
    unsigned r;
    asm("cvt.rn.f16x2.f32 %0, %1, %2;" : "=r"(r) : "f"(hi), "f"(lo));
    return r;
}
__device__ __forceinline__ unsigned h2ex2(unsigned x) {
    unsigned y;
    asm("ex2.approx.f16x2 %0, %1;" : "=r"(y) : "r"(x));
    return y;
}

__device__ __forceinline__ void mma_f16(float c[4],
                                        unsigned a0, unsigned a1,
                                        unsigned a2, unsigned a3,
                                        unsigned b0, unsigned b1) {
    asm volatile(
        "mma.sync.aligned.m16n8k16.row.col.f32.f16.f16.f32 "
        "{%0,%1,%2,%3}, {%4,%5,%6,%7}, {%8,%9}, {%0,%1,%2,%3};"
        : "+f"(c[0]), "+f"(c[1]), "+f"(c[2]), "+f"(c[3])
        : "r"(a0), "r"(a1), "r"(a2), "r"(a3), "r"(b0), "r"(b1));
}

__device__ __forceinline__ uint32_t smem_u32(const void* p) {
    uint32_t a;
    asm("{ .reg .u64 t; cvta.to.shared.u64 t, %1; cvt.u32.u64 %0, t; }"
        : "=r"(a) : "l"(p));
    return a;
}

__device__ __forceinline__ void ldsm_x4(uint32_t addr, unsigned& r0,
                                        unsigned& r1, unsigned& r2,
                                        unsigned& r3) {
    asm volatile(
        "ldmatrix.sync.aligned.m8n8.x4.shared.b16 {%0,%1,%2,%3}, [%4];"
        : "=r"(r0), "=r"(r1), "=r"(r2), "=r"(r3) : "r"(addr));
}

__device__ __forceinline__ void ldsm_x4_t(uint32_t addr, unsigned& r0,
                                          unsigned& r1, unsigned& r2,
                                          unsigned& r3) {
    asm volatile(
        "ldmatrix.sync.aligned.m8n8.x4.trans.shared.b16 {%0,%1,%2,%3}, [%4];"
        : "=r"(r0), "=r"(r1), "=r"(r2), "=r"(r3) : "r"(addr));
}

__device__ __forceinline__ void cpa16(uint32_t dst, const void* src) {
    asm volatile("cp.async.cg.shared.global [%0], [%1], 16;"
                 :: "r"(dst), "l"(src) : "memory");
}
__device__ __forceinline__ void cp_commit() {
    asm volatile("cp.async.commit_group;" ::: "memory");
}
__device__ __forceinline__ void cp_waitall() {
    asm volatile("cp.async.wait_group 0;" ::: "memory");
}

#define QSCALE 0.18033688011112042f   /* 0.125 * log2(e) */
#define ONESH2 0x3C003C00u            /* half2(1.0, 1.0) */

// ---------------------------------------------------------------------------
// Pre-split kernel (identical to R11)
// ---------------------------------------------------------------------------
__global__ void split_kernel(const float4* __restrict__ src,
                             uint4* __restrict__ hi,
                             uint4* __restrict__ lo, int n8)
{
    int i = blockIdx.x * blockDim.x + threadIdx.x;
    if (i >= n8) return;
    float4 v0 = src[2 * i];
    float4 v1 = src[2 * i + 1];
    uint4 h, l;
    split2(v0.x, v0.y, h.x, l.x);
    split2(v0.z, v0.w, h.y, l.y);
    split2(v1.x, v1.y, h.z, l.z);
    split2(v1.z, v1.w, h.w, l.w);
    hi[i] = h;
    lo[i] = l;
}

// ---------------------------------------------------------------------------
// Split-fp16 GEMM (identical to R11): 256x128 tile, 256 thr / 8 warps,
// warp tile 64x64, cp.async double-buffer + ldmatrix.
// MODE 0: C fp32 [m][n] (out projection)
// MODE 3: plain fp16 -> ohi head layout (V proj)
// MODE 4: RoPE fused, hi-only fp16 -> ohi head layout (Q and K proj)
// ---------------------------------------------------------------------------
#define G_STAGE 61440
#define G_AHI   0
#define G_ALO   20480
#define G_BHI   40960
#define G_BLO   51200
#define G_SMEM  (2 * G_STAGE)   /* 122880 */

template <int MODE>
__global__ void __launch_bounds__(256)
gemm_cp_kernel(const __half* __restrict__ Ahi, const __half* __restrict__ Alo,
               const __half* __restrict__ Whi, const __half* __restrict__ Wlo,
               const float* __restrict__ bias,
               const float* __restrict__ cosb, const float* __restrict__ sinb,
               float scale, float* __restrict__ outf,
               __half* __restrict__ ohi)
{
    extern __shared__ __align__(128) char smem[];
    const int tid  = threadIdx.x;
    const int warp = tid >> 5;
    const int lane = tid & 31;
    const int g = lane >> 2;
    const int t = lane & 3;
    const int wm = (warp & 3) * 64;
    const int wn = (warp >> 2) * 64;
    const int bm = blockIdx.y * 256;
    const int bn = blockIdx.x * 128;
    const uint32_t sb = smem_u32(smem);

    float acc[4][8][4];
#pragma unroll
    for (int i = 0; i < 4; i++)
#pragma unroll
        for (int j = 0; j < 8; j++)
#pragma unroll
            for (int c = 0; c < 4; c++) acc[i][j][c] = 0.f;

    const int lrow = tid >> 2;
    const int lch  = tid & 3;
#define G_ISSUE(IT)                                                          \
    do {                                                                     \
        const int kt_ = (IT) * 32;                                           \
        const uint32_t base_ = sb + ((IT) & 1) * G_STAGE;                    \
        _Pragma("unroll")                                                    \
        for (int p_ = 0; p_ < 4; p_++) {                                     \
            const int row_ = lrow + p_ * 64;                                 \
            const uint32_t d_ = row_ * 80 + lch * 16;                        \
            const size_t sa_ = (size_t)(bm + row_) * DM + kt_ + lch * 8;     \
            cpa16(base_ + G_AHI + d_, Ahi + sa_);                            \
            cpa16(base_ + G_ALO + d_, Alo + sa_);                            \
        }                                                                    \
        _Pragma("unroll")                                                    \
        for (int p_ = 0; p_ < 2; p_++) {                                     \
            const int row_ = lrow + p_ * 64;                                 \
            const uint32_t d_ = row_ * 80 + lch * 16;                        \
            const size_t sb_ = (size_t)(bn + row_) * DM + kt_ + lch * 8;     \
            cpa16(base_ + G_BHI + d_, Whi + sb_);                            \
            cpa16(base_ + G_BLO + d_, Wlo + sb_);                            \
        }                                                                    \
        cp_commit();                                                         \
    } while (0)

    G_ISSUE(0);
    cp_waitall();
    __syncthreads();

    for (int it = 0; it < 32; it++) {
        const uint32_t abase = sb + (it & 1) * G_STAGE;
        if (it < 31) G_ISSUE(it + 1);

#pragma unroll
        for (int kk = 0; kk < 2; kk++) {
            const uint32_t acol = kk * 32 + (lane & 16);
            const uint32_t arow = (lane & 15);
            unsigned ah[4][4], al[4][4];
#pragma unroll
            for (int i = 0; i < 4; i++) {
                const uint32_t ro = (uint32_t)(wm + 16 * i + arow) * 80 + acol;
                ldsm_x4(abase + G_AHI + ro, ah[i][0], ah[i][1], ah[i][2], ah[i][3]);
                ldsm_x4(abase + G_ALO + ro, al[i][0], al[i][1], al[i][2], al[i][3]);
            }
            const uint32_t brow = (lane & 7) + ((lane >> 4) << 3);
            const uint32_t bcol = kk * 32 + (lane & 8) * 2;
#pragma unroll
            for (int jp = 0; jp < 4; jp++) {
                const uint32_t ro = (uint32_t)(wn + 16 * jp + brow) * 80 + bcol;
                unsigned h0, h1, h2, h3, l0, l1, l2, l3;
                ldsm_x4(abase + G_BHI + ro, h0, h1, h2, h3);
                ldsm_x4(abase + G_BLO + ro, l0, l1, l2, l3);
#pragma unroll
                for (int i = 0; i < 4; i++) {
                    mma_f16(acc[i][2 * jp],     ah[i][0], ah[i][1], ah[i][2], ah[i][3], h0, h1);
                    mma_f16(acc[i][2 * jp],     ah[i][0], ah[i][1], ah[i][2], ah[i][3], l0, l1);
                    mma_f16(acc[i][2 * jp],     al[i][0], al[i][1], al[i][2], al[i][3], h0, h1);
                    mma_f16(acc[i][2 * jp + 1], ah[i][0], ah[i][1], ah[i][2], ah[i][3], h2, h3);
                    mma_f16(acc[i][2 * jp + 1], ah[i][0], ah[i][1], ah[i][2], ah[i][3], l2, l3);
                    mma_f16(acc[i][2 * jp + 1], al[i][0], al[i][1], al[i][2], al[i][3], h2, h3);
                }
            }
        }
        if (it < 31) { cp_waitall(); __syncthreads(); }
    }

    // ---- Epilogues ----
    const int h = (bn + wn) >> 6;

    if (MODE == 0) {
#pragma unroll
        for (int i = 0; i < 4; i++) {
#pragma unroll
            for (int j = 0; j < 8; j++) {
                const int n = bn + wn + 8 * j + 2 * t;
                const float b0 = bias[n];
                const float b1 = bias[n + 1];
#pragma unroll
                for (int half = 0; half < 2; half++) {
                    const int m = bm + wm + 16 * i + g + half * 8;
                    float2 val;
                    val.x = acc[i][j][half * 2 + 0] + b0;
                    val.y = acc[i][j][half * 2 + 1] + b1;
                    *reinterpret_cast<float2*>(outf + (size_t)m * DM + n) = val;
                }
            }
        }
    } else if (MODE == 4) {
#pragma unroll
        for (int i = 0; i < 4; i++) {
#pragma unroll
            for (int half = 0; half < 2; half++) {
                const int m = bm + wm + 16 * i + g + half * 8;
                const int b = m >> 11;
                const int l = m & (LQ - 1);
                const size_t rowoff = (((size_t)(b * NH + h)) * LQ + l) * HD;
                const float* cr = cosb + ((size_t)b * LQ + l) * HD;
                const float* sr = sinb + ((size_t)b * LQ + l) * HD;
#pragma unroll
                for (int j = 0; j < 4; j++) {
                    const int dd = 8 * j + 2 * t;
                    const int n1 = bn + wn + dd;
                    float x1a = acc[i][j][half * 2 + 0] + bias[n1];
                    float x1b = acc[i][j][half * 2 + 1] + bias[n1 + 1];
                    float x2a = acc[i][j + 4][half * 2 + 0] + bias[n1 + 32];
                    float x2b = acc[i][j + 4][half * 2 + 1] + bias[n1 + 33];
                    float y1a = (x1a * cr[dd]      - x2a * sr[dd])      * scale;
                    float y1b = (x1b * cr[dd + 1]  - x2b * sr[dd + 1])  * scale;
                    float y2a = (x2a * cr[dd + 32] + x1a * sr[dd + 32]) * scale;
                    float y2b = (x2b * cr[dd + 33] + x1b * sr[dd + 33]) * scale;
                    *reinterpret_cast<unsigned*>(ohi + rowoff + dd) =
                        pack_h2(__float2half_rn(y1a), __float2half_rn(y1b));
                    *reinterpret_cast<unsigned*>(ohi + rowoff + dd + 32) =
                        pack_h2(__float2half_rn(y2a), __float2half_rn(y2b));
                }
            }
        }
    } else {  // MODE 3
#pragma unroll
        for (int i = 0; i < 4; i++) {
#pragma unroll
            for (int half = 0; half < 2; half++) {
                const int m = bm + wm + 16 * i + g + half * 8;
                const int b = m >> 11;
                const int l = m & (LQ - 1);
                const size_t rowoff = (((size_t)(b * NH + h)) * LQ + l) * HD;
#pragma unroll
                for (int j = 0; j < 8; j++) {
                    const int dd = 8 * j + 2 * t;
                    const int n = bn + wn + dd;
                    float vx = acc[i][j][half * 2 + 0] + bias[n];
                    float vy = acc[i][j][half * 2 + 1] + bias[n + 1];
                    *reinterpret_cast<unsigned*>(ohi + rowoff + dd) =
                        pack_h2(__float2half_rn(vx), __float2half_rn(vy));
                }
            }
        }
    }
#undef G_ISSUE
}

// ---------------------------------------------------------------------------
// Flash attention (identical to R11)
// ---------------------------------------------------------------------------
#define F_STG   18496
#define F_QHI   0
#define F_KHI(s) (9216 + (s) * F_STG)
#define F_VH(s)  (F_KHI(s) + 9216)
#define F_MSK(s) (F_KHI(s) + 18432)
#define F_SMEM  (9216 + 2 * F_STG)   /* 46208 */

__global__ void __launch_bounds__(128)
flash_bk64_kernel(const __half* __restrict__ qhi,
                  const __half* __restrict__ khi,
                  const __half* __restrict__ vh,
                  const unsigned char* __restrict__ mask,
                  __half* __restrict__ chi, __half* __restrict__ clo)
{
    extern __shared__ __align__(128) char smem[];
    const int tid  = threadIdx.x;
    const int warp = tid >> 5;
    const int lane = tid & 31;
    const int g = lane >> 2;
    const int t = lane & 3;
    const int m0 = warp * 16;

    const int bh = blockIdx.y;
    const int b  = bh >> 4;
    const int h  = bh & 15;
    const int q0 = blockIdx.x * 64;
    const uint32_t sb = smem_u32(smem);

    const __half* qh_g = qhi + (((size_t)bh) * LQ + q0) * HD;
    const size_t kvbase = ((size_t)bh) * LK * HD;

    const int lrow = tid >> 3;
    const int lch  = tid & 7;

#define F_ISSUE(IT)                                                          \
    do {                                                                     \
        const int kt_ = (IT) * 64;                                           \
        const int st_ = (IT) & 1;                                            \
        _Pragma("unroll")                                                    \
        for (int p_ = 0; p_ < 4; p_++) {                                     \
            const int row_ = lrow + p_ * 16;                                 \
            const uint32_t d_ = row_ * 144 + lch * 16;                       \
            const size_t s_ = kvbase + (size_t)(kt_ + row_) * HD + lch * 8;  \
            cpa16(sb + F_KHI(st_) + d_, khi + s_);                           \
            cpa16(sb + F_VH(st_)  + d_, vh  + s_);                           \
        }                                                                    \
        if (tid < 4)                                                         \
            cpa16(sb + F_MSK(st_) + tid * 16,                                \
                  mask + (size_t)b * LK + kt_ + tid * 16);                   \
        cp_commit();                                                         \
    } while (0)

#pragma unroll
    for (int p = 0; p < 4; p++) {
        const int row = lrow + p * 16;
        const uint32_t d = row * 144 + lch * 16;
        cpa16(sb + F_QHI + d, qh_g + (size_t)row * HD + lch * 8);
    }
    F_ISSUE(0);
    cp_waitall();
    __syncthreads();

    unsigned qh[4][4];
    {
        const uint32_t qoff = (uint32_t)(m0 + (lane & 15)) * 144 + (lane & 16);
#pragma unroll
        for (int kk = 0; kk < 4; kk++)
            ldsm_x4(sb + F_QHI + qoff + kk * 32,
                    qh[kk][0], qh[kk][1], qh[kk][2], qh[kk][3]);
    }

    float m_[2] = { -1e30f, -1e30f };
    float l_[2] = { 0.f, 0.f };
    float o[8][4];
#pragma unroll
    for (int n = 0; n < 8; n++)
#pragma unroll
        for (int c = 0; c < 4; c++) o[n][c] = 0.f;

    for (int it = 0; it < LK / 64; it++) {
        const int st = it & 1;
        if (it < LK / 64 - 1) F_ISSUE(it + 1);

        float s[8][4];
#pragma unroll
        for (int j = 0; j < 8; j++)
#pragma unroll
            for (int c = 0; c < 4; c++) s[j][c] = 0.f;

        const uint32_t krow = (lane & 7) + ((lane >> 4) << 3);
#pragma unroll
        for (int kk = 0; kk < 4; kk++) {
            const uint32_t kcol = kk * 32 + (lane & 8) * 2;
#pragma unroll
            for (int jp = 0; jp < 4; jp++) {
                const uint32_t ro = (uint32_t)(jp * 16 + krow) * 144 + kcol;
                unsigned h0, h1, h2, h3;
                ldsm_x4(sb + F_KHI(st) + ro, h0, h1, h2, h3);
                mma_f16(s[2 * jp],     qh[kk][0], qh[kk][1], qh[kk][2], qh[kk][3], h0, h1);
                mma_f16(s[2 * jp + 1], qh[kk][0], qh[kk][1], qh[kk][2], qh[kk][3], h2, h3);
            }
        }

        const unsigned char* msk =
            reinterpret_cast<const unsigned char*>(smem) + F_MSK(st);
#pragma unroll
        for (int j = 0; j < 8; j++) {
            const int col = j * 8 + 2 * t;
            if (msk[col])     { s[j][0] = -1e30f; s[j][2] = -1e30f; }
            if (msk[col + 1]) { s[j][1] = -1e30f; s[j][3] = -1e30f; }
        }

        float r0 = -1e30f, r1 = -1e30f;
#pragma unroll
        for (int j = 0; j < 8; j++) {
            r0 = fmaxf(r0, fmaxf(s[j][0], s[j][1]));
            r1 = fmaxf(r1, fmaxf(s[j][2], s[j][3]));
        }
        r0 = fmaxf(r0, __shfl_xor_sync(0xffffffffu, r0, 1));
        r0 = fmaxf(r0, __shfl_xor_sync(0xffffffffu, r0, 2));
        r1 = fmaxf(r1, __shfl_xor_sync(0xffffffffu, r1, 1));
        r1 = fmaxf(r1, __shfl_xor_sync(0xffffffffu, r1, 2));

        const float mn0 = fmaxf(m_[0], r0);
        const float mn1 = fmaxf(m_[1], r1);
        const float alpha0 = ex2f(m_[0] - mn0);
        const float alpha1 = ex2f(m_[1] - mn1);
        m_[0] = mn0; m_[1] = mn1;

        unsigned ph0[8], ph1[8];
#pragma unroll
        for (int j = 0; j < 8; j++) {
            ph0[j] = h2ex2(f22h2(s[j][0] - mn0, s[j][1] - mn0));
            ph1[j] = h2ex2(f22h2(s[j][2] - mn1, s[j][3] - mn1));
        }

#pragma unroll
        for (int n = 0; n < 8; n++) {
            o[n][0] *= alpha0; o[n][1] *= alpha0;
            o[n][2] *= alpha1; o[n][3] *= alpha1;
        }

        float c_l[4] = { 0.f, 0.f, 0.f, 0.f };
        const uint32_t vrow = (lane & 15);
        const uint32_t vcolb = (lane & 16);
#pragma unroll
        for (int kk = 0; kk < 4; kk++) {
            const unsigned a0 = ph0[2 * kk];
            const unsigned a1 = ph1[2 * kk];
            const unsigned a2 = ph0[2 * kk + 1];
            const unsigned a3 = ph1[2 * kk + 1];
            const uint32_t rbase = (uint32_t)(kk * 16 + vrow) * 144 + vcolb;
#pragma unroll
            for (int np = 0; np < 4; np++) {
                unsigned r0v, r1v, r2v, r3v;
                ldsm_x4_t(sb + F_VH(st) + rbase + np * 32, r0v, r1v, r2v, r3v);
                mma_f16(o[2 * np],     a0, a1, a2, a3, r0v, r1v);
                mma_f16(o[2 * np + 1], a0, a1, a2, a3, r2v, r3v);
            }
            mma_f16(c_l, a0, a1, a2, a3, ONESH2, ONESH2);
        }
        l_[0] = l_[0] * alpha0 + c_l[0];
        l_[1] = l_[1] * alpha1 + c_l[2];

        if (it < LK / 64 - 1) { cp_waitall(); __syncthreads(); }
    }

    const float inv0 = 1.f / l_[0];
    const float inv1 = 1.f / l_[1];
#pragma unroll
    for (int n = 0; n < 8; n++) {
        const int col = h * HD + n * 8 + 2 * t;
        const int row0 = q0 + m0 + g;
        const size_t off0 = ((size_t)b * LQ + row0) * DM + col;
        const size_t off1 = ((size_t)b * LQ + row0 + 8) * DM + col;
        unsigned hi0, lo0, hi1, lo1;
        split2(o[n][0] * inv0, o[n][1] * inv0, hi0, lo0);
        split2(o[n][2] * inv1, o[n][3] * inv1, hi1, lo1);
        *reinterpret_cast<unsigned*>(chi + off0) = hi0;
        *reinterpret_cast<unsigned*>(clo + off0) = lo0;
        *reinterpret_cast<unsigned*>(chi + off1) = hi1;
        *reinterpret_cast<unsigned*>(clo + off1) = lo1;
    }
#undef F_ISSUE
}

// ---------------------------------------------------------------------------
// Launch: 4-branch capture DAG. Streams/events created ONCE (first call =
// correctness run) so the capture call performs zero driver allocations.
// The enqueued work DAG is identical on every call.
// ---------------------------------------------------------------------------
extern "C" void kernel_launch(void* const* d_in, const int* in_sizes, int n_in,
                              void* d_out, int out_size)
{
    const float* query = (const float*)d_in[0];
    const float* key   = (const float*)d_in[1];
    const float* value = (const float*)d_in[2];
    const float* cos_q = (const float*)d_in[3];
    const float* sin_q = (const float*)d_in[4];
    const float* cos_k = (const float*)d_in[5];
    const float* sin_k = (const float*)d_in[6];
    const unsigned char* mask = (const unsigned char*)d_in[7];
    const float* Wq = (const float*)d_in[8];
    const float* bq = (const float*)d_in[9];
    const float* Wk = (const float*)d_in[10];
    const float* bk = (const float*)d_in[11];
    const float* Wv = (const float*)d_in[12];
    const float* bv = (const float*)d_in[13];
    const float* Wo = (const float*)d_in[14];
    const float* bo = (const float*)d_in[15];
    float* out = (float*)d_out;

    __half *aAhi, *aAlo, *aBhi, *aBlo, *aChi, *aClo;
    __half *wAhi, *wAlo, *wBhi, *wBlo, *wChi, *wClo, *wDhi, *wDlo;
    __half *pqhi, *pkhi, *pvh, *pchi, *pclo;
    cudaGetSymbolAddress((void**)&aAhi, g_aAhi);
    cudaGetSymbolAddress((void**)&aAlo, g_aAlo);
    cudaGetSymbolAddress((void**)&aBhi, g_aBhi);
    cudaGetSymbolAddress((void**)&aBlo, g_aBlo);
    cudaGetSymbolAddress((void**)&aChi, g_aChi);
    cudaGetSymbolAddress((void**)&aClo, g_aClo);
    cudaGetSymbolAddress((void**)&wAhi, g_wAhi);
    cudaGetSymbolAddress((void**)&wAlo, g_wAlo);
    cudaGetSymbolAddress((void**)&wBhi, g_wBhi);
    cudaGetSymbolAddress((void**)&wBlo, g_wBlo);
    cudaGetSymbolAddress((void**)&wChi, g_wChi);
    cudaGetSymbolAddress((void**)&wClo, g_wClo);
    cudaGetSymbolAddress((void**)&wDhi, g_wDhi);
    cudaGetSymbolAddress((void**)&wDlo, g_wDlo);
    cudaGetSymbolAddress((void**)&pqhi, g_qhi);
    cudaGetSymbolAddress((void**)&pkhi, g_khi);
    cudaGetSymbolAddress((void**)&pvh,  g_vh);
    cudaGetSymbolAddress((void**)&pchi, g_chi);
    cudaGetSymbolAddress((void**)&pclo, g_clo);

    // One-time resource creation (outside any capture: first call is the
    // plain correctness run). Subsequent calls allocate NOTHING.
    static cudaStream_t s1 = nullptr, s2 = nullptr, s3 = nullptr;
    static cudaEvent_t eroot = nullptr, evK = nullptr, evV = nullptr,
                       evO = nullptr;
    static bool attrs_set = false;
    if (s1 == nullptr) {
        cudaStreamCreateWithFlags(&s1, cudaStreamNonBlocking);
        cudaStreamCreateWithFlags(&s2, cudaStreamNonBlocking);
        cudaStreamCreateWithFlags(&s3, cudaStreamNonBlocking);
        cudaEventCreateWithFlags(&eroot, cudaEventDisableTiming);
        cudaEventCreateWithFlags(&evK,   cudaEventDisableTiming);
        cudaEventCreateWithFlags(&evV,   cudaEventDisableTiming);
        cudaEventCreateWithFlags(&evO,   cudaEventDisableTiming);
    }
    if (!attrs_set) {
        cudaFuncSetAttribute(gemm_cp_kernel<0>,
                             cudaFuncAttributeMaxDynamicSharedMemorySize, G_SMEM);
        cudaFuncSetAttribute(gemm_cp_kernel<3>,
                             cudaFuncAttributeMaxDynamicSharedMemorySize, G_SMEM);
        cudaFuncSetAttribute(gemm_cp_kernel<4>,
                             cudaFuncAttributeMaxDynamicSharedMemorySize, G_SMEM);
        cudaFuncSetAttribute(flash_bk64_kernel,
                             cudaFuncAttributeMaxDynamicSharedMemorySize, F_SMEM);
        attrs_set = true;
    }

    const int nA8 = MTOT * DM / 8;
    const int nW8 = DM * DM / 8;
    const int gA = (nA8 + 255) / 256;
    const int gW = (nW8 + 255) / 256;
    dim3 gg(DM / 128, MTOT / 256);   // (8, 32)

    // Fork all side streams from the capture (default) stream.
    cudaEventRecord(eroot, 0);
    cudaStreamWaitEvent(s1, eroot, 0);
    cudaStreamWaitEvent(s2, eroot, 0);
    cudaStreamWaitEvent(s3, eroot, 0);

    // Branch 1 (s1): K chain — splits + gemmK
    split_kernel<<<gA, 256, 0, s1>>>((const float4*)key,
                                     (uint4*)aBhi, (uint4*)aBlo, nA8);
    split_kernel<<<gW, 256, 0, s1>>>((const float4*)Wk,
                                     (uint4*)wBhi, (uint4*)wBlo, nW8);
    gemm_cp_kernel<4><<<gg, 256, G_SMEM, s1>>>(aBhi, aBlo, wBhi, wBlo, bk,
                                               cos_k, sin_k, 1.0f,
                                               nullptr, pkhi);
    cudaEventRecord(evK, s1);

    // Branch 2 (s2): V chain — splits + gemmV
    split_kernel<<<gA, 256, 0, s2>>>((const float4*)value,
                                     (uint4*)aChi, (uint4*)aClo, nA8);
    split_kernel<<<gW, 256, 0, s2>>>((const float4*)Wv,
                                     (uint4*)wChi, (uint4*)wClo, nW8);
    gemm_cp_kernel<3><<<gg, 256, G_SMEM, s2>>>(aChi, aClo, wChi, wClo, bv,
                                               nullptr, nullptr, 1.0f,
                                               nullptr, pvh);
    cudaEventRecord(evV, s2);

    // Branch 3 (s3): Wo split (independent until gemmO)
    split_kernel<<<gW, 256, 0, s3>>>((const float4*)Wo,
                                     (uint4*)wDhi, (uint4*)wDlo, nW8);
    cudaEventRecord(evO, s3);

    // Branch 0 (s0): Q chain — splits + gemmQ
    split_kernel<<<gA, 256>>>((const float4*)query,
                              (uint4*)aAhi, (uint4*)aAlo, nA8);
    split_kernel<<<gW, 256>>>((const float4*)Wq,
                              (uint4*)wAhi, (uint4*)wAlo, nW8);
    gemm_cp_kernel<4><<<gg, 256, G_SMEM>>>(aAhi, aAlo, wAhi, wAlo, bq,
                                           cos_q, sin_q, QSCALE,
                                           nullptr, pqhi);

    // Join K and V branches; flash on s0.
    cudaStreamWaitEvent(0, evK, 0);
    cudaStreamWaitEvent(0, evV, 0);
    flash_bk64_kernel<<<dim3(LQ / 64, BB * NH), 128, F_SMEM>>>(
        pqhi, pkhi, pvh, mask, pchi, pclo);

    // Join Wo branch; output projection on s0.
    cudaStreamWaitEvent(0, evO, 0);
    gemm_cp_kernel<0><<<gg, 256, G_SMEM>>>(pchi, pclo, wDhi, wDlo, bo,
                                           nullptr, nullptr, 1.0f,
                                           out, nullptr);
}

// round 17
// speedup vs baseline: 1.5188x; 1.5188x over previous
#include <cuda_runtime.h>
#include <cuda_fp16.h>
#include <math.h>
#include <stdint.h>

// Problem constants
#define BB   4
#define NH   16
#define HD   64
#define DM   1024
#define LQ   2048
#define LK   2048
#define MTOT (BB * LQ)

// ---------------------------------------------------------------------------
// Scratch (device globals — no allocation allowed).
// Dual-buffered A/W split outputs so side-stream splits overlap GEMMs.
// ---------------------------------------------------------------------------
__device__ __half g_aAhi[MTOT * DM];
__device__ __half g_aAlo[MTOT * DM];
__device__ __half g_aBhi[MTOT * DM];
__device__ __half g_aBlo[MTOT * DM];
__device__ __half g_wAhi[DM * DM];
__device__ __half g_wAlo[DM * DM];
__device__ __half g_wBhi[DM * DM];
__device__ __half g_wBlo[DM * DM];
__device__ __half g_qhi[BB * NH * LQ * HD];
__device__ __half g_khi[BB * NH * LK * HD];
__device__ __half g_vh [BB * NH * LK * HD];
__device__ __half g_chi[MTOT * DM];
__device__ __half g_clo[MTOT * DM];

// ---------------------------------------------------------------------------
// Helpers (identical to R11/R14)
// ---------------------------------------------------------------------------
__device__ __forceinline__ unsigned pack_h2(__half a, __half b) {
    return (unsigned)__half_as_ushort(a) | ((unsigned)__half_as_ushort(b) << 16);
}

__device__ __forceinline__ void split2(float x, float y,
                                       unsigned& hi, unsigned& lo) {
    __half hx = __float2half_rn(x);
    __half hy = __float2half_rn(y);
    __half lx = __float2half_rn(x - __half2float(hx));
    __half ly = __float2half_rn(y - __half2float(hy));
    hi = pack_h2(hx, hy);
    lo = pack_h2(lx, ly);
}

__device__ __forceinline__ float ex2f(float x) {
    float y;
    asm("ex2.approx.ftz.f32 %0, %1;" : "=f"(y) : "f"(x));
    return y;
}

__device__ __forceinline__ unsigned f22h2(float lo, float hi) {
    unsigned r;
    asm("cvt.rn.f16x2.f32 %0, %1, %2;" : "=r"(r) : "f"(hi), "f"(lo));
    return r;
}
__device__ __forceinline__ unsigned h2ex2(unsigned x) {
    unsigned y;
    asm("ex2.approx.f16x2 %0, %1;" : "=r"(y) : "r"(x));
    return y;
}

__device__ __forceinline__ void mma_f16(float c[4],
                                        unsigned a0, unsigned a1,
                                        unsigned a2, unsigned a3,
                                        unsigned b0, unsigned b1) {
    asm volatile(
        "mma.sync.aligned.m16n8k16.row.col.f32.f16.f16.f32 "
        "{%0,%1,%2,%3}, {%4,%5,%6,%7}, {%8,%9}, {%0,%1,%2,%3};"
        : "+f"(c[0]), "+f"(c[1]), "+f"(c[2]), "+f"(c[3])
        : "r"(a0), "r"(a1), "r"(a2), "r"(a3), "r"(b0), "r"(b1));
}

__device__ __forceinline__ uint32_t smem_u32(const void* p) {
    uint32_t a;
    asm("{ .reg .u64 t; cvta.to.shared.u64 t, %1; cvt.u32.u64 %0, t; }"
        : "=r"(a) : "l"(p));
    return a;
}

__device__ __forceinline__ void ldsm_x4(uint32_t addr, unsigned& r0,
                                        unsigned& r1, unsigned& r2,
                                        unsigned& r3) {
    asm volatile(
        "ldmatrix.sync.aligned.m8n8.x4.shared.b16 {%0,%1,%2,%3}, [%4];"
        : "=r"(r0), "=r"(r1), "=r"(r2), "=r"(r3) : "r"(addr));
}

__device__ __forceinline__ void ldsm_x4_t(uint32_t addr, unsigned& r0,
                                          unsigned& r1, unsigned& r2,
                                          unsigned& r3) {
    asm volatile(
        "ldmatrix.sync.aligned.m8n8.x4.trans.shared.b16 {%0,%1,%2,%3}, [%4];"
        : "=r"(r0), "=r"(r1), "=r"(r2), "=r"(r3) : "r"(addr));
}

__device__ __forceinline__ void cpa16(uint32_t dst, const void* src) {
    asm volatile("cp.async.cg.shared.global [%0], [%1], 16;"
                 :: "r"(dst), "l"(src) : "memory");
}
__device__ __forceinline__ void cp_commit() {
    asm volatile("cp.async.commit_group;" ::: "memory");
}
__device__ __forceinline__ void cp_waitall() {
    asm volatile("cp.async.wait_group 0;" ::: "memory");
}

#define QSCALE 0.18033688011112042f   /* 0.125 * log2(e) */
#define ONESH2 0x3C003C00u            /* half2(1.0, 1.0) */

// ---------------------------------------------------------------------------
// Pre-split kernel (identical to R11)
// ---------------------------------------------------------------------------
__global__ void split_kernel(const float4* __restrict__ src,
                             uint4* __restrict__ hi,
                             uint4* __restrict__ lo, int n8)
{
    int i = blockIdx.x * blockDim.x + threadIdx.x;
    if (i >= n8) return;
    float4 v0 = src[2 * i];
    float4 v1 = src[2 * i + 1];
    uint4 h, l;
    split2(v0.x, v0.y, h.x, l.x);
    split2(v0.z, v0.w, h.y, l.y);
    split2(v1.x, v1.y, h.z, l.z);
    split2(v1.z, v1.w, h.w, l.w);
    hi[i] = h;
    lo[i] = l;
}

// ---------------------------------------------------------------------------
// Split-fp16 GEMM (identical to R11): 256x128 tile, 256 thr / 8 warps,
// warp tile 64x64, cp.async double-buffer + ldmatrix.
// MODE 0: C fp32 [m][n] (out projection)
// MODE 3: plain fp16 -> ohi head layout (V proj)
// MODE 4: RoPE fused, hi-only fp16 -> ohi head layout (Q and K proj)
// ---------------------------------------------------------------------------
#define G_STAGE 61440
#define G_AHI   0
#define G_ALO   20480
#define G_BHI   40960
#define G_BLO   51200
#define G_SMEM  (2 * G_STAGE)   /* 122880 */

template <int MODE>
__global__ void __launch_bounds__(256)
gemm_cp_kernel(const __half* __restrict__ Ahi, const __half* __restrict__ Alo,
               const __half* __restrict__ Whi, const __half* __restrict__ Wlo,
               const float* __restrict__ bias,
               const float* __restrict__ cosb, const float* __restrict__ sinb,
               float scale, float* __restrict__ outf,
               __half* __restrict__ ohi)
{
    extern __shared__ __align__(128) char smem[];
    const int tid  = threadIdx.x;
    const int warp = tid >> 5;
    const int lane = tid & 31;
    const int g = lane >> 2;
    const int t = lane & 3;
    const int wm = (warp & 3) * 64;
    const int wn = (warp >> 2) * 64;
    const int bm = blockIdx.y * 256;
    const int bn = blockIdx.x * 128;
    const uint32_t sb = smem_u32(smem);

    float acc[4][8][4];
#pragma unroll
    for (int i = 0; i < 4; i++)
#pragma unroll
        for (int j = 0; j < 8; j++)
#pragma unroll
            for (int c = 0; c < 4; c++) acc[i][j][c] = 0.f;

    const int lrow = tid >> 2;
    const int lch  = tid & 3;
#define G_ISSUE(IT)                                                          \
    do {                                                                     \
        const int kt_ = (IT) * 32;                                           \
        const uint32_t base_ = sb + ((IT) & 1) * G_STAGE;                    \
        _Pragma("unroll")                                                    \
        for (int p_ = 0; p_ < 4; p_++) {                                     \
            const int row_ = lrow + p_ * 64;                                 \
            const uint32_t d_ = row_ * 80 + lch * 16;                        \
            const size_t sa_ = (size_t)(bm + row_) * DM + kt_ + lch * 8;     \
            cpa16(base_ + G_AHI + d_, Ahi + sa_);                            \
            cpa16(base_ + G_ALO + d_, Alo + sa_);                            \
        }                                                                    \
        _Pragma("unroll")                                                    \
        for (int p_ = 0; p_ < 2; p_++) {                                     \
            const int row_ = lrow + p_ * 64;                                 \
            const uint32_t d_ = row_ * 80 + lch * 16;                        \
            const size_t sb_ = (size_t)(bn + row_) * DM + kt_ + lch * 8;     \
            cpa16(base_ + G_BHI + d_, Whi + sb_);                            \
            cpa16(base_ + G_BLO + d_, Wlo + sb_);                            \
        }                                                                    \
        cp_commit();                                                         \
    } while (0)

    G_ISSUE(0);
    cp_waitall();
    __syncthreads();

    for (int it = 0; it < 32; it++) {
        const uint32_t abase = sb + (it & 1) * G_STAGE;
        if (it < 31) G_ISSUE(it + 1);

#pragma unroll
        for (int kk = 0; kk < 2; kk++) {
            const uint32_t acol = kk * 32 + (lane & 16);
            const uint32_t arow = (lane & 15);
            unsigned ah[4][4], al[4][4];
#pragma unroll
            for (int i = 0; i < 4; i++) {
                const uint32_t ro = (uint32_t)(wm + 16 * i + arow) * 80 + acol;
                ldsm_x4(abase + G_AHI + ro, ah[i][0], ah[i][1], ah[i][2], ah[i][3]);
                ldsm_x4(abase + G_ALO + ro, al[i][0], al[i][1], al[i][2], al[i][3]);
            }
            const uint32_t brow = (lane & 7) + ((lane >> 4) << 3);
            const uint32_t bcol = kk * 32 + (lane & 8) * 2;
#pragma unroll
            for (int jp = 0; jp < 4; jp++) {
                const uint32_t ro = (uint32_t)(wn + 16 * jp + brow) * 80 + bcol;
                unsigned h0, h1, h2, h3, l0, l1, l2, l3;
                ldsm_x4(abase + G_BHI + ro, h0, h1, h2, h3);
                ldsm_x4(abase + G_BLO + ro, l0, l1, l2, l3);
#pragma unroll
                for (int i = 0; i < 4; i++) {
                    mma_f16(acc[i][2 * jp],     ah[i][0], ah[i][1], ah[i][2], ah[i][3], h0, h1);
                    mma_f16(acc[i][2 * jp],     ah[i][0], ah[i][1], ah[i][2], ah[i][3], l0, l1);
                    mma_f16(acc[i][2 * jp],     al[i][0], al[i][1], al[i][2], al[i][3], h0, h1);
                    mma_f16(acc[i][2 * jp + 1], ah[i][0], ah[i][1], ah[i][2], ah[i][3], h2, h3);
                    mma_f16(acc[i][2 * jp + 1], ah[i][0], ah[i][1], ah[i][2], ah[i][3], l2, l3);
                    mma_f16(acc[i][2 * jp + 1], al[i][0], al[i][1], al[i][2], al[i][3], h2, h3);
                }
            }
        }
        if (it < 31) { cp_waitall(); __syncthreads(); }
    }

    // ---- Epilogues ----
    const int h = (bn + wn) >> 6;

    if (MODE == 0) {
#pragma unroll
        for (int i = 0; i < 4; i++) {
#pragma unroll
            for (int j = 0; j < 8; j++) {
                const int n = bn + wn + 8 * j + 2 * t;
                const float b0 = bias[n];
                const float b1 = bias[n + 1];
#pragma unroll
                for (int half = 0; half < 2; half++) {
                    const int m = bm + wm + 16 * i + g + half * 8;
                    float2 val;
                    val.x = acc[i][j][half * 2 + 0] + b0;
                    val.y = acc[i][j][half * 2 + 1] + b1;
                    *reinterpret_cast<float2*>(outf + (size_t)m * DM + n) = val;
                }
            }
        }
    } else if (MODE == 4) {
#pragma unroll
        for (int i = 0; i < 4; i++) {
#pragma unroll
            for (int half = 0; half < 2; half++) {
                const int m = bm + wm + 16 * i + g + half * 8;
                const int b = m >> 11;
                const int l = m & (LQ - 1);
                const size_t rowoff = (((size_t)(b * NH + h)) * LQ + l) * HD;
                const float* cr = cosb + ((size_t)b * LQ + l) * HD;
                const float* sr = sinb + ((size_t)b * LQ + l) * HD;
#pragma unroll
                for (int j = 0; j < 4; j++) {
                    const int dd = 8 * j + 2 * t;
                    const int n1 = bn + wn + dd;
                    float x1a = acc[i][j][half * 2 + 0] + bias[n1];
                    float x1b = acc[i][j][half * 2 + 1] + bias[n1 + 1];
                    float x2a = acc[i][j + 4][half * 2 + 0] + bias[n1 + 32];
                    float x2b = acc[i][j + 4][half * 2 + 1] + bias[n1 + 33];
                    float y1a = (x1a * cr[dd]      - x2a * sr[dd])      * scale;
                    float y1b = (x1b * cr[dd + 1]  - x2b * sr[dd + 1])  * scale;
                    float y2a = (x2a * cr[dd + 32] + x1a * sr[dd + 32]) * scale;
                    float y2b = (x2b * cr[dd + 33] + x1b * sr[dd + 33]) * scale;
                    *reinterpret_cast<unsigned*>(ohi + rowoff + dd) =
                        pack_h2(__float2half_rn(y1a), __float2half_rn(y1b));
                    *reinterpret_cast<unsigned*>(ohi + rowoff + dd + 32) =
                        pack_h2(__float2half_rn(y2a), __float2half_rn(y2b));
                }
            }
        }
    } else {  // MODE 3
#pragma unroll
        for (int i = 0; i < 4; i++) {
#pragma unroll
            for (int half = 0; half < 2; half++) {
                const int m = bm + wm + 16 * i + g + half * 8;
                const int b = m >> 11;
                const int l = m & (LQ - 1);
                const size_t rowoff = (((size_t)(b * NH + h)) * LQ + l) * HD;
#pragma unroll
                for (int j = 0; j < 8; j++) {
                    const int dd = 8 * j + 2 * t;
                    const int n = bn + wn + dd;
                    float vx = acc[i][j][half * 2 + 0] + bias[n];
                    float vy = acc[i][j][half * 2 + 1] + bias[n + 1];
                    *reinterpret_cast<unsigned*>(ohi + rowoff + dd) =
                        pack_h2(__float2half_rn(vx), __float2half_rn(vy));
                }
            }
        }
    }
#undef G_ISSUE
}

// ---------------------------------------------------------------------------
// Flash attention (identical to R11)
// ---------------------------------------------------------------------------
#define F_STG   18496
#define F_QHI   0
#define F_KHI(s) (9216 + (s) * F_STG)
#define F_VH(s)  (F_KHI(s) + 9216)
#define F_MSK(s) (F_KHI(s) + 18432)
#define F_SMEM  (9216 + 2 * F_STG)   /* 46208 */

__global__ void __launch_bounds__(128)
flash_bk64_kernel(const __half* __restrict__ qhi,
                  const __half* __restrict__ khi,
                  const __half* __restrict__ vh,
                  const unsigned char* __restrict__ mask,
                  __half* __restrict__ chi, __half* __restrict__ clo)
{
    extern __shared__ __align__(128) char smem[];
    const int tid  = threadIdx.x;
    const int warp = tid >> 5;
    const int lane = tid & 31;
    const int g = lane >> 2;
    const int t = lane & 3;
    const int m0 = warp * 16;

    const int bh = blockIdx.y;
    const int b  = bh >> 4;
    const int h  = bh & 15;
    const int q0 = blockIdx.x * 64;
    const uint32_t sb = smem_u32(smem);

    const __half* qh_g = qhi + (((size_t)bh) * LQ + q0) * HD;
    const size_t kvbase = ((size_t)bh) * LK * HD;

    const int lrow = tid >> 3;
    const int lch  = tid & 7;

#define F_ISSUE(IT)                                                          \
    do {                                                                     \
        const int kt_ = (IT) * 64;                                           \
        const int st_ = (IT) & 1;                                            \
        _Pragma("unroll")                                                    \
        for (int p_ = 0; p_ < 4; p_++) {                                     \
            const int row_ = lrow + p_ * 16;                                 \
            const uint32_t d_ = row_ * 144 + lch * 16;                       \
            const size_t s_ = kvbase + (size_t)(kt_ + row_) * HD + lch * 8;  \
            cpa16(sb + F_KHI(st_) + d_, khi + s_);                           \
            cpa16(sb + F_VH(st_)  + d_, vh  + s_);                           \
        }                                                                    \
        if (tid < 4)                                                         \
            cpa16(sb + F_MSK(st_) + tid * 16,                                \
                  mask + (size_t)b * LK + kt_ + tid * 16);                   \
        cp_commit();                                                         \
    } while (0)

#pragma unroll
    for (int p = 0; p < 4; p++) {
        const int row = lrow + p * 16;
        const uint32_t d = row * 144 + lch * 16;
        cpa16(sb + F_QHI + d, qh_g + (size_t)row * HD + lch * 8);
    }
    F_ISSUE(0);
    cp_waitall();
    __syncthreads();

    unsigned qh[4][4];
    {
        const uint32_t qoff = (uint32_t)(m0 + (lane & 15)) * 144 + (lane & 16);
#pragma unroll
        for (int kk = 0; kk < 4; kk++)
            ldsm_x4(sb + F_QHI + qoff + kk * 32,
                    qh[kk][0], qh[kk][1], qh[kk][2], qh[kk][3]);
    }

    float m_[2] = { -1e30f, -1e30f };
    float l_[2] = { 0.f, 0.f };
    float o[8][4];
#pragma unroll
    for (int n = 0; n < 8; n++)
#pragma unroll
        for (int c = 0; c < 4; c++) o[n][c] = 0.f;

    for (int it = 0; it < LK / 64; it++) {
        const int st = it & 1;
        if (it < LK / 64 - 1) F_ISSUE(it + 1);

        float s[8][4];
#pragma unroll
        for (int j = 0; j < 8; j++)
#pragma unroll
            for (int c = 0; c < 4; c++) s[j][c] = 0.f;

        const uint32_t krow = (lane & 7) + ((lane >> 4) << 3);
#pragma unroll
        for (int kk = 0; kk < 4; kk++) {
            const uint32_t kcol = kk * 32 + (lane & 8) * 2;
#pragma unroll
            for (int jp = 0; jp < 4; jp++) {
                const uint32_t ro = (uint32_t)(jp * 16 + krow) * 144 + kcol;
                unsigned h0, h1, h2, h3;
                ldsm_x4(sb + F_KHI(st) + ro, h0, h1, h2, h3);
                mma_f16(s[2 * jp],     qh[kk][0], qh[kk][1], qh[kk][2], qh[kk][3], h0, h1);
                mma_f16(s[2 * jp + 1], qh[kk][0], qh[kk][1], qh[kk][2], qh[kk][3], h2, h3);
            }
        }

        const unsigned char* msk =
            reinterpret_cast<const unsigned char*>(smem) + F_MSK(st);
#pragma unroll
        for (int j = 0; j < 8; j++) {
            const int col = j * 8 + 2 * t;
            if (msk[col])     { s[j][0] = -1e30f; s[j][2] = -1e30f; }
            if (msk[col + 1]) { s[j][1] = -1e30f; s[j][3] = -1e30f; }
        }

        float r0 = -1e30f, r1 = -1e30f;
#pragma unroll
        for (int j = 0; j < 8; j++) {
            r0 = fmaxf(r0, fmaxf(s[j][0], s[j][1]));
            r1 = fmaxf(r1, fmaxf(s[j][2], s[j][3]));
        }
        r0 = fmaxf(r0, __shfl_xor_sync(0xffffffffu, r0, 1));
        r0 = fmaxf(r0, __shfl_xor_sync(0xffffffffu, r0, 2));
        r1 = fmaxf(r1, __shfl_xor_sync(0xffffffffu, r1, 1));
        r1 = fmaxf(r1, __shfl_xor_sync(0xffffffffu, r1, 2));

        const float mn0 = fmaxf(m_[0], r0);
        const float mn1 = fmaxf(m_[1], r1);
        const float alpha0 = ex2f(m_[0] - mn0);
        const float alpha1 = ex2f(m_[1] - mn1);
        m_[0] = mn0; m_[1] = mn1;

        unsigned ph0[8], ph1[8];
#pragma unroll
        for (int j = 0; j < 8; j++) {
            ph0[j] = h2ex2(f22h2(s[j][0] - mn0, s[j][1] - mn0));
            ph1[j] = h2ex2(f22h2(s[j][2] - mn1, s[j][3] - mn1));
        }

#pragma unroll
        for (int n = 0; n < 8; n++) {
            o[n][0] *= alpha0; o[n][1] *= alpha0;
            o[n][2] *= alpha1; o[n][3] *= alpha1;
        }

        float c_l[4] = { 0.f, 0.f, 0.f, 0.f };
        const uint32_t vrow = (lane & 15);
        const uint32_t vcolb = (lane & 16);
#pragma unroll
        for (int kk = 0; kk < 4; kk++) {
            const unsigned a0 = ph0[2 * kk];
            const unsigned a1 = ph1[2 * kk];
            const unsigned a2 = ph0[2 * kk + 1];
            const unsigned a3 = ph1[2 * kk + 1];
            const uint32_t rbase = (uint32_t)(kk * 16 + vrow) * 144 + vcolb;
#pragma unroll
            for (int np = 0; np < 4; np++) {
                unsigned r0v, r1v, r2v, r3v;
                ldsm_x4_t(sb + F_VH(st) + rbase + np * 32, r0v, r1v, r2v, r3v);
                mma_f16(o[2 * np],     a0, a1, a2, a3, r0v, r1v);
                mma_f16(o[2 * np + 1], a0, a1, a2, a3, r2v, r3v);
            }
            mma_f16(c_l, a0, a1, a2, a3, ONESH2, ONESH2);
        }
        l_[0] = l_[0] * alpha0 + c_l[0];
        l_[1] = l_[1] * alpha1 + c_l[2];

        if (it < LK / 64 - 1) { cp_waitall(); __syncthreads(); }
    }

    const float inv0 = 1.f / l_[0];
    const float inv1 = 1.f / l_[1];
#pragma unroll
    for (int n = 0; n < 8; n++) {
        const int col = h * HD + n * 8 + 2 * t;
        const int row0 = q0 + m0 + g;
        const size_t off0 = ((size_t)b * LQ + row0) * DM + col;
        const size_t off1 = ((size_t)b * LQ + row0 + 8) * DM + col;
        unsigned hi0, lo0, hi1, lo1;
        split2(o[n][0] * inv0, o[n][1] * inv0, hi0, lo0);
        split2(o[n][2] * inv1, o[n][3] * inv1, hi1, lo1);
        *reinterpret_cast<unsigned*>(chi + off0) = hi0;
        *reinterpret_cast<unsigned*>(clo + off0) = lo0;
        *reinterpret_cast<unsigned*>(chi + off1) = hi1;
        *reinterpret_cast<unsigned*>(clo + off1) = lo1;
    }
#undef F_ISSUE
}

// ---------------------------------------------------------------------------
// Launch: R14 DAG (GEMMs serialized on s0; splits pipelined on one side
// stream). Static handles -> zero driver allocations on the capture call.
// Prologue tweak: Q-act split on s0 parallel with Wq split on s2.
// ---------------------------------------------------------------------------
extern "C" void kernel_launch(void* const* d_in, const int* in_sizes, int n_in,
                              void* d_out, int out_size)
{
    const float* query = (const float*)d_in[0];
    const float* key   = (const float*)d_in[1];
    const float* value = (const float*)d_in[2];
    const float* cos_q = (const float*)d_in[3];
    const float* sin_q = (const float*)d_in[4];
    const float* cos_k = (const float*)d_in[5];
    const float* sin_k = (const float*)d_in[6];
    const unsigned char* mask = (const unsigned char*)d_in[7];
    const float* Wq = (const float*)d_in[8];
    const float* bq = (const float*)d_in[9];
    const float* Wk = (const float*)d_in[10];
    const float* bk = (const float*)d_in[11];
    const float* Wv = (const float*)d_in[12];
    const float* bv = (const float*)d_in[13];
    const float* Wo = (const float*)d_in[14];
    const float* bo = (const float*)d_in[15];
    float* out = (float*)d_out;

    __half *aAhi, *aAlo, *aBhi, *aBlo, *wAhi, *wAlo, *wBhi, *wBlo;
    __half *pqhi, *pkhi, *pvh, *pchi, *pclo;
    cudaGetSymbolAddress((void**)&aAhi, g_aAhi);
    cudaGetSymbolAddress((void**)&aAlo, g_aAlo);
    cudaGetSymbolAddress((void**)&aBhi, g_aBhi);
    cudaGetSymbolAddress((void**)&aBlo, g_aBlo);
    cudaGetSymbolAddress((void**)&wAhi, g_wAhi);
    cudaGetSymbolAddress((void**)&wAlo, g_wAlo);
    cudaGetSymbolAddress((void**)&wBhi, g_wBhi);
    cudaGetSymbolAddress((void**)&wBlo, g_wBlo);
    cudaGetSymbolAddress((void**)&pqhi, g_qhi);
    cudaGetSymbolAddress((void**)&pkhi, g_khi);
    cudaGetSymbolAddress((void**)&pvh,  g_vh);
    cudaGetSymbolAddress((void**)&pchi, g_chi);
    cudaGetSymbolAddress((void**)&pclo, g_clo);

    // One-time resource creation (first call = plain correctness run, where
    // driver-side pool growth is allowed). Capture calls allocate NOTHING.
    static cudaStream_t s2 = nullptr;
    static cudaEvent_t eroot = nullptr, evWq = nullptr, evK = nullptr,
                       evV = nullptr, evO = nullptr, egQ = nullptr,
                       egK = nullptr;
    if (s2 == nullptr) {
        cudaStreamCreateWithFlags(&s2, cudaStreamNonBlocking);
        cudaEventCreateWithFlags(&eroot, cudaEventDisableTiming);
        cudaEventCreateWithFlags(&evWq,  cudaEventDisableTiming);
        cudaEventCreateWithFlags(&evK,   cudaEventDisableTiming);
        cudaEventCreateWithFlags(&evV,   cudaEventDisableTiming);
        cudaEventCreateWithFlags(&evO,   cudaEventDisableTiming);
        cudaEventCreateWithFlags(&egQ,   cudaEventDisableTiming);
        cudaEventCreateWithFlags(&egK,   cudaEventDisableTiming);
        cudaFuncSetAttribute(gemm_cp_kernel<0>,
                             cudaFuncAttributeMaxDynamicSharedMemorySize, G_SMEM);
        cudaFuncSetAttribute(gemm_cp_kernel<3>,
                             cudaFuncAttributeMaxDynamicSharedMemorySize, G_SMEM);
        cudaFuncSetAttribute(gemm_cp_kernel<4>,
                             cudaFuncAttributeMaxDynamicSharedMemorySize, G_SMEM);
        cudaFuncSetAttribute(flash_bk64_kernel,
                             cudaFuncAttributeMaxDynamicSharedMemorySize, F_SMEM);
    }

    const int nA8 = MTOT * DM / 8;
    const int nW8 = DM * DM / 8;
    const int gA = (nA8 + 255) / 256;
    const int gW = (nW8 + 255) / 256;
    dim3 gg(DM / 128, MTOT / 256);   // (8, 32)

    // Fork s2 from the (captured) default stream.
    cudaEventRecord(eroot, 0);
    cudaStreamWaitEvent(s2, eroot, 0);

    // Prologue in parallel: Q-act split on s0, Wq split on s2.
    split_kernel<<<gA, 256>>>((const float4*)query,
                              (uint4*)aAhi, (uint4*)aAlo, nA8);
    split_kernel<<<gW, 256, 0, s2>>>((const float4*)Wq,
                                     (uint4*)wAhi, (uint4*)wAlo, nW8);
    cudaEventRecord(evWq, s2);

    // s2: K-stage splits (B-set buffers).
    split_kernel<<<gA, 256, 0, s2>>>((const float4*)key,
                                     (uint4*)aBhi, (uint4*)aBlo, nA8);
    split_kernel<<<gW, 256, 0, s2>>>((const float4*)Wk,
                                     (uint4*)wBhi, (uint4*)wBlo, nW8);
    cudaEventRecord(evK, s2);

    // s0: Q projection (+RoPE, hi only, 0.125*log2e folded).
    cudaStreamWaitEvent(0, evWq, 0);
    gemm_cp_kernel<4><<<gg, 256, G_SMEM>>>(aAhi, aAlo, wAhi, wAlo, bq,
                                           cos_q, sin_q, QSCALE,
                                           nullptr, pqhi);
    cudaEventRecord(egQ, 0);

    // s2: V-stage splits (reuse A-set; must wait for gemmQ).
    cudaStreamWaitEvent(s2, egQ, 0);
    split_kernel<<<gA, 256, 0, s2>>>((const float4*)value,
                                     (uint4*)aAhi, (uint4*)aAlo, nA8);
    split_kernel<<<gW, 256, 0, s2>>>((const float4*)Wv,
                                     (uint4*)wAhi, (uint4*)wAlo, nW8);
    cudaEventRecord(evV, s2);

    // s0: K projection (+RoPE, hi only).
    cudaStreamWaitEvent(0, evK, 0);
    gemm_cp_kernel<4><<<gg, 256, G_SMEM>>>(aBhi, aBlo, wBhi, wBlo, bk,
                                           cos_k, sin_k, 1.0f,
                                           nullptr, pkhi);
    cudaEventRecord(egK, 0);

    // s2: Wo split (reuses B-set W buffers; must wait for gemmK).
    cudaStreamWaitEvent(s2, egK, 0);
    split_kernel<<<gW, 256, 0, s2>>>((const float4*)Wo,
                                     (uint4*)wBhi, (uint4*)wBlo, nW8);
    cudaEventRecord(evO, s2);

    // s0: V projection (fp16 direct).
    cudaStreamWaitEvent(0, evV, 0);
    gemm_cp_kernel<3><<<gg, 256, G_SMEM>>>(aAhi, aAlo, wAhi, wAlo, bv,
                                           nullptr, nullptr, 1.0f,
                                           nullptr, pvh);

    // s0: Attention (writes split ctx directly).
    flash_bk64_kernel<<<dim3(LQ / 64, BB * NH), 128, F_SMEM>>>(
        pqhi, pkhi, pvh, mask, pchi, pclo);

    // s0: Output projection (A = split ctx, W = wB set).
    cudaStreamWaitEvent(0, evO, 0);
    gemm_cp_kernel<0><<<gg, 256, G_SMEM>>>(pchi, pclo, wBhi, wBlo, bo,
                                           nullptr, nullptr, 1.0f,
                                           out, nullptr);
}